// round 16
// baseline (speedup 1.0000x reference)
#include <cuda_runtime.h>
#include <cuda_fp16.h>
#include <cstdint>
#include <cstddef>

#define MAXN 50000
#define MAXE 800000
#define NF   128
#define NOUT 64
#define SCAN_B 512
#define FUSE_BLOCKS 592

// Scratch (no allocations allowed -> __device__ globals).
__device__ uint2 g_y1h[(size_t)MAXN * NF / 4];    // x @ W1^T            (half)
__device__ uint2 g_y2h[(size_t)MAXN * NOUT / 4];  // A@relu(s1) @ W2^T   (half)
__device__ int   g_deg[MAXN];                     // degree counts, then write-cursor
__device__ int   g_off[MAXN + 1];                 // CSR row offsets (by dst)
__device__ int   g_bsum[SCAN_B];                  // scan block sums
__device__ int2  g_edges[MAXE];                   // {src, __float_as_int(val)} by dst

// ---------------------------------------------------------------------------
// CSR build: histogram -> scan1 (per-block) -> scan23 (apply) -> permute
// ---------------------------------------------------------------------------
__global__ void hist_kernel(const int* __restrict__ dst, int E) {
    int i = blockIdx.x * blockDim.x + threadIdx.x;
    if (i < E) atomicAdd(&g_deg[__ldg(dst + i)], 1);
}

__global__ __launch_bounds__(SCAN_B) void scan1_kernel(int n) {
    __shared__ int sh[SCAN_B];
    int t = threadIdx.x;
    int i = blockIdx.x * SCAN_B + t;
    int v = (i < n) ? g_deg[i] : 0;
    sh[t] = v;
    __syncthreads();
#pragma unroll
    for (int o = 1; o < SCAN_B; o <<= 1) {
        int u = (t >= o) ? sh[t - o] : 0;
        __syncthreads();
        sh[t] += u;
        __syncthreads();
    }
    if (i <= n && i < MAXN + 1) g_off[i] = sh[t] - v;
    if (t == SCAN_B - 1) g_bsum[blockIdx.x] = sh[t];
}

__global__ void scan23_kernel(int n, int nb, int E) {
    __shared__ int pref[256];
    int t = threadIdx.x;
    if (t == 0) {
        int run = 0;
        for (int b = 0; b < nb; ++b) { pref[b] = run; run += g_bsum[b]; }
    }
    __syncthreads();
    int i = blockIdx.x * blockDim.x + t;
    if (i < n) {
        int o = g_off[i] + pref[i >> 9];
        g_off[i] = o;
        g_deg[i] = o;
    }
    if (i == 0) g_off[n] = E;
}

__global__ void permute_kernel(const int* __restrict__ src, const int* __restrict__ dst,
                               const float* __restrict__ vals, int E) {
    int e = blockIdx.x * blockDim.x + threadIdx.x;
    if (e >= E) return;
    int pos = atomicAdd(&g_deg[__ldg(dst + e)], 1);
    g_edges[pos] = make_int2(__ldg(src + e), __float_as_int(__ldg(vals + e)));
}

// ---------------------------------------------------------------------------
// bf16 / mma / ldmatrix helpers (layer-1 GEMM)
// ---------------------------------------------------------------------------
__device__ __forceinline__ uint32_t bf16x2_rn(float f0, float f1) {
    uint32_t r;
    asm("cvt.rn.bf16x2.f32 %0, %1, %2;" : "=r"(r) : "f"(f1), "f"(f0));
    return r;
}

template <bool RELU>
__device__ __forceinline__ void cvt8_bf(const float* v, uint32_t* hw, uint32_t* lw) {
#pragma unroll
    for (int p = 0; p < 4; ++p) {
        float f0 = v[2 * p], f1 = v[2 * p + 1];
        if (RELU) { f0 = fmaxf(f0, 0.f); f1 = fmaxf(f1, 0.f); }
        uint32_t h = bf16x2_rn(f0, f1);
        float h0 = __uint_as_float(h << 16);
        float h1 = __uint_as_float(h & 0xFFFF0000u);
        uint32_t l = bf16x2_rn(f0 - h0, f1 - h1);
        hw[p] = h; lw[p] = l;
    }
}

__device__ __forceinline__ void mma_bf16(float* d, const uint32_t* a, uint32_t b0, uint32_t b1) {
    asm volatile(
        "mma.sync.aligned.m16n8k16.row.col.f32.bf16.bf16.f32 "
        "{%0,%1,%2,%3}, {%4,%5,%6,%7}, {%8,%9}, {%0,%1,%2,%3};"
        : "+f"(d[0]), "+f"(d[1]), "+f"(d[2]), "+f"(d[3])
        : "r"(a[0]), "r"(a[1]), "r"(a[2]), "r"(a[3]), "r"(b0), "r"(b1));
}

__device__ __forceinline__ void ldm_x4(uint32_t* r, uint32_t saddr) {
    asm volatile("ldmatrix.sync.aligned.m8n8.x4.shared.b16 {%0,%1,%2,%3}, [%4];"
                 : "=r"(r[0]), "=r"(r[1]), "=r"(r[2]), "=r"(r[3]) : "r"(saddr));
}

// ---------------------------------------------------------------------------
// C[M, 128] (fp16) = A[M, 128] @ W[128, 128]^T via 3xBF16 MMA (hi/lo split).
// ---------------------------------------------------------------------------
template <int NCOLS, bool RELU_IN>
__global__ __launch_bounds__(256) void gemm_tc_kernel(
    const float* __restrict__ A, const float* __restrict__ W,
    __half* __restrict__ C, int M)
{
    constexpr int BK   = 32;
    constexpr int STRD = 20;
    constexpr int NT   = NCOLS / 16;

    __shared__ __align__(16) uint32_t As_hi[128 * STRD];
    __shared__ __align__(16) uint32_t As_lo[128 * STRD];
    __shared__ __align__(16) uint32_t Bs_hi[NCOLS * STRD];
    __shared__ __align__(16) uint32_t Bs_lo[NCOLS * STRD];

    const int tid  = threadIdx.x;
    const int wid  = tid >> 5;
    const int lane = tid & 31;
    const int g    = lane >> 2;
    const int t    = lane & 3;
    const int warp_m = wid >> 1;
    const int warp_n = wid & 1;
    const int blockRow = blockIdx.x * 128;

    float acc[2][NT][4];
#pragma unroll
    for (int mt = 0; mt < 2; ++mt)
#pragma unroll
        for (int nt = 0; nt < NT; ++nt)
#pragma unroll
            for (int i = 0; i < 4; ++i) acc[mt][nt][i] = 0.f;

    const uint32_t sAhi = (uint32_t)__cvta_generic_to_shared(As_hi);
    const uint32_t sAlo = (uint32_t)__cvta_generic_to_shared(As_lo);
    const uint32_t sBhi = (uint32_t)__cvta_generic_to_shared(Bs_hi);
    const uint32_t sBlo = (uint32_t)__cvta_generic_to_shared(Bs_lo);

    const int  arow  = tid >> 1;
    const int  akoff = (tid & 1) * 16;
    const int  gArow = blockRow + arow;
    const bool aok   = (gArow < M);

    const int a_lr = lane & 15;
    const int a_kb = (lane >> 4) * 16;
    const int b_lr = (lane & 7) + ((lane >> 4) << 3);
    const int b_kb = ((lane >> 3) & 1) * 16;

    for (int k0 = 0; k0 < 128; k0 += BK) {
        {
            float v[16];
#pragma unroll
            for (int j = 0; j < 16; ++j) v[j] = 0.f;
            if (aok) {
                const float* ap = A + (size_t)gArow * 128 + k0 + akoff;
                *reinterpret_cast<float4*>(v)      = *reinterpret_cast<const float4*>(ap);
                *reinterpret_cast<float4*>(v + 4)  = *reinterpret_cast<const float4*>(ap + 4);
                *reinterpret_cast<float4*>(v + 8)  = *reinterpret_cast<const float4*>(ap + 8);
                *reinterpret_cast<float4*>(v + 12) = *reinterpret_cast<const float4*>(ap + 12);
            }
            uint32_t hw[8], lw[8];
            cvt8_bf<RELU_IN>(v, hw, lw);
            cvt8_bf<RELU_IN>(v + 8, hw + 4, lw + 4);
            int wo = arow * STRD + (akoff >> 1);
            *reinterpret_cast<uint4*>(&As_hi[wo])     = make_uint4(hw[0], hw[1], hw[2], hw[3]);
            *reinterpret_cast<uint4*>(&As_hi[wo + 4]) = make_uint4(hw[4], hw[5], hw[6], hw[7]);
            *reinterpret_cast<uint4*>(&As_lo[wo])     = make_uint4(lw[0], lw[1], lw[2], lw[3]);
            *reinterpret_cast<uint4*>(&As_lo[wo + 4]) = make_uint4(lw[4], lw[5], lw[6], lw[7]);
        }
        {
            int brow  = tid >> 1;
            int bkoff = (tid & 1) * 16;
            float v[16];
            const float* wp = W + (size_t)brow * 128 + k0 + bkoff;
            *reinterpret_cast<float4*>(v)      = *reinterpret_cast<const float4*>(wp);
            *reinterpret_cast<float4*>(v + 4)  = *reinterpret_cast<const float4*>(wp + 4);
            *reinterpret_cast<float4*>(v + 8)  = *reinterpret_cast<const float4*>(wp + 8);
            *reinterpret_cast<float4*>(v + 12) = *reinterpret_cast<const float4*>(wp + 12);
            uint32_t hw[8], lw[8];
            cvt8_bf<false>(v, hw, lw);
            cvt8_bf<false>(v + 8, hw + 4, lw + 4);
            int wo = brow * STRD + (bkoff >> 1);
            *reinterpret_cast<uint4*>(&Bs_hi[wo])     = make_uint4(hw[0], hw[1], hw[2], hw[3]);
            *reinterpret_cast<uint4*>(&Bs_hi[wo + 4]) = make_uint4(hw[4], hw[5], hw[6], hw[7]);
            *reinterpret_cast<uint4*>(&Bs_lo[wo])     = make_uint4(lw[0], lw[1], lw[2], lw[3]);
            *reinterpret_cast<uint4*>(&Bs_lo[wo + 4]) = make_uint4(lw[4], lw[5], lw[6], lw[7]);
        }
        __syncthreads();

#pragma unroll
        for (int ks = 0; ks < 2; ++ks) {
            const int kbyte = ks * 32;
            uint32_t ah[2][4], al[2][4];
#pragma unroll
            for (int mt = 0; mt < 2; ++mt) {
                uint32_t off = (uint32_t)((warp_m * 32 + mt * 16 + a_lr) * STRD) * 4u + kbyte + a_kb;
                ldm_x4(ah[mt], sAhi + off);
                ldm_x4(al[mt], sAlo + off);
            }
#pragma unroll
            for (int ntp = 0; ntp < NT / 2; ++ntp) {
                int nbase = warp_n * (NCOLS / 2) + ntp * 16;
                uint32_t off = (uint32_t)((nbase + b_lr) * STRD) * 4u + kbyte + b_kb;
                uint32_t bh[4], bl[4];
                ldm_x4(bh, sBhi + off);
                ldm_x4(bl, sBlo + off);
#pragma unroll
                for (int mt = 0; mt < 2; ++mt) {
                    mma_bf16(acc[mt][2 * ntp],     ah[mt], bh[0], bh[1]);
                    mma_bf16(acc[mt][2 * ntp],     ah[mt], bl[0], bl[1]);
                    mma_bf16(acc[mt][2 * ntp],     al[mt], bh[0], bh[1]);
                    mma_bf16(acc[mt][2 * ntp + 1], ah[mt], bh[2], bh[3]);
                    mma_bf16(acc[mt][2 * ntp + 1], ah[mt], bl[2], bl[3]);
                    mma_bf16(acc[mt][2 * ntp + 1], al[mt], bh[2], bh[3]);
                }
            }
        }
        __syncthreads();
    }

#pragma unroll
    for (int mt = 0; mt < 2; ++mt) {
#pragma unroll
        for (int half = 0; half < 2; ++half) {
            int row = blockRow + warp_m * 32 + mt * 16 + half * 8 + g;
            if (row < M) {
#pragma unroll
                for (int nt = 0; nt < NT; ++nt) {
                    int col = warp_n * (NCOLS / 2) + nt * 8 + 2 * t;
                    __half2 h = __float22half2_rn(
                        make_float2(acc[mt][nt][half * 2], acc[mt][nt][half * 2 + 1]));
                    *reinterpret_cast<__half2*>(C + (size_t)row * NCOLS + col) = h;
                }
            }
        }
    }
}

// ---------------------------------------------------------------------------
// FUSED: y2[d] = relu(sum_e val*y1[src]) @ W2^T, warp per node (grid-strided).
// Gather phase identical to old gather128; epilogue does the 128->64 dot in
// fp32 against W2 staged in smem. Eliminates the s1 buffer + gemm64 kernel.
// ---------------------------------------------------------------------------
__global__ __launch_bounds__(256) void gather_gemm64_kernel(
    const __half* __restrict__ Y, const float* __restrict__ W2,
    __half* __restrict__ y2, int n)
{
    __shared__ float W2s[128 * 66];   // [k][c] transposed, padded
    __shared__ float rowbuf[8][128];  // per-warp relu'd s1 row

    const int tid  = threadIdx.x;
    const int wid  = tid >> 5;
    const int lane = tid & 31;

    // Stage W2 (W2[c][k] row-major -> W2s[k*66 + c])
    for (int i = tid; i < 64 * 128; i += 256) {
        int c = i >> 7, k = i & 127;
        W2s[k * 66 + c] = W2[i];
    }
    __syncthreads();

    for (int d = blockIdx.x * 8 + wid; d < n; d += gridDim.x * 8) {
        int beg = g_off[d], end = g_off[d + 1];

        // ---- gather phase (fp16 y1, fp32 accumulate) ----
        float4 acc = make_float4(0.f, 0.f, 0.f, 0.f);
        int e = beg;
        for (; e + 3 < end; e += 4) {
            int2 p0 = __ldg(&g_edges[e]);
            int2 p1 = __ldg(&g_edges[e + 1]);
            int2 p2 = __ldg(&g_edges[e + 2]);
            int2 p3 = __ldg(&g_edges[e + 3]);
            uint2 u0 = __ldg(reinterpret_cast<const uint2*>(Y + (size_t)p0.x * 128) + lane);
            uint2 u1 = __ldg(reinterpret_cast<const uint2*>(Y + (size_t)p1.x * 128) + lane);
            uint2 u2 = __ldg(reinterpret_cast<const uint2*>(Y + (size_t)p2.x * 128) + lane);
            uint2 u3 = __ldg(reinterpret_cast<const uint2*>(Y + (size_t)p3.x * 128) + lane);
            float v0 = __int_as_float(p0.y), v1 = __int_as_float(p1.y);
            float v2 = __int_as_float(p2.y), v3 = __int_as_float(p3.y);
            float2 a0 = __half22float2(*reinterpret_cast<__half2*>(&u0.x));
            float2 b0 = __half22float2(*reinterpret_cast<__half2*>(&u0.y));
            float2 a1 = __half22float2(*reinterpret_cast<__half2*>(&u1.x));
            float2 b1 = __half22float2(*reinterpret_cast<__half2*>(&u1.y));
            float2 a2 = __half22float2(*reinterpret_cast<__half2*>(&u2.x));
            float2 b2 = __half22float2(*reinterpret_cast<__half2*>(&u2.y));
            float2 a3 = __half22float2(*reinterpret_cast<__half2*>(&u3.x));
            float2 b3 = __half22float2(*reinterpret_cast<__half2*>(&u3.y));
            acc.x = fmaf(v0, a0.x, acc.x); acc.y = fmaf(v0, a0.y, acc.y);
            acc.z = fmaf(v0, b0.x, acc.z); acc.w = fmaf(v0, b0.y, acc.w);
            acc.x = fmaf(v1, a1.x, acc.x); acc.y = fmaf(v1, a1.y, acc.y);
            acc.z = fmaf(v1, b1.x, acc.z); acc.w = fmaf(v1, b1.y, acc.w);
            acc.x = fmaf(v2, a2.x, acc.x); acc.y = fmaf(v2, a2.y, acc.y);
            acc.z = fmaf(v2, b2.x, acc.z); acc.w = fmaf(v2, b2.y, acc.w);
            acc.x = fmaf(v3, a3.x, acc.x); acc.y = fmaf(v3, a3.y, acc.y);
            acc.z = fmaf(v3, b3.x, acc.z); acc.w = fmaf(v3, b3.y, acc.w);
        }
        for (; e < end; ++e) {
            int2 p = __ldg(&g_edges[e]);
            float v = __int_as_float(p.y);
            uint2 u = __ldg(reinterpret_cast<const uint2*>(Y + (size_t)p.x * 128) + lane);
            float2 a = __half22float2(*reinterpret_cast<__half2*>(&u.x));
            float2 b = __half22float2(*reinterpret_cast<__half2*>(&u.y));
            acc.x = fmaf(v, a.x, acc.x); acc.y = fmaf(v, a.y, acc.y);
            acc.z = fmaf(v, b.x, acc.z); acc.w = fmaf(v, b.y, acc.w);
        }

        // ---- relu + stage row (lane holds cols [4*lane, 4*lane+3]) ----
        float4 r = make_float4(fmaxf(acc.x, 0.f), fmaxf(acc.y, 0.f),
                               fmaxf(acc.z, 0.f), fmaxf(acc.w, 0.f));
        *reinterpret_cast<float4*>(&rowbuf[wid][lane * 4]) = r;
        __syncwarp();

        // ---- fp32 dot: lane computes output cols 2*lane, 2*lane+1 ----
        float o0 = 0.f, o1 = 0.f;
        const float* rb = rowbuf[wid];
#pragma unroll 8
        for (int k = 0; k < 128; k += 4) {
            float4 s = *reinterpret_cast<const float4*>(rb + k);
            float2 w0 = *reinterpret_cast<const float2*>(&W2s[(k + 0) * 66 + 2 * lane]);
            float2 w1 = *reinterpret_cast<const float2*>(&W2s[(k + 1) * 66 + 2 * lane]);
            float2 w2 = *reinterpret_cast<const float2*>(&W2s[(k + 2) * 66 + 2 * lane]);
            float2 w3 = *reinterpret_cast<const float2*>(&W2s[(k + 3) * 66 + 2 * lane]);
            o0 = fmaf(s.x, w0.x, o0); o1 = fmaf(s.x, w0.y, o1);
            o0 = fmaf(s.y, w1.x, o0); o1 = fmaf(s.y, w1.y, o1);
            o0 = fmaf(s.z, w2.x, o0); o1 = fmaf(s.z, w2.y, o1);
            o0 = fmaf(s.w, w3.x, o0); o1 = fmaf(s.w, w3.y, o1);
        }
        *reinterpret_cast<__half2*>(y2 + (size_t)d * 64 + 2 * lane) =
            __float22half2_rn(make_float2(o0, o1));
        __syncwarp();   // rowbuf reuse guard
    }
}

// ---------------------------------------------------------------------------
// Gather SPMM, 64-wide fp16 input, fused row softmax: warp/node, 2 halfs/lane.
// ---------------------------------------------------------------------------
__global__ __launch_bounds__(256) void gather64_softmax_kernel(
    const __half* __restrict__ Y, float* __restrict__ out, int n)
{
    int gid  = blockIdx.x * blockDim.x + threadIdx.x;
    int d    = gid >> 5;
    int lane = threadIdx.x & 31;
    if (d >= n) return;
    int beg = g_off[d], end = g_off[d + 1];

    float2 acc = make_float2(0.f, 0.f);
    int e = beg;
    for (; e + 3 < end; e += 4) {
        int2 p0 = __ldg(&g_edges[e]);
        int2 p1 = __ldg(&g_edges[e + 1]);
        int2 p2 = __ldg(&g_edges[e + 2]);
        int2 p3 = __ldg(&g_edges[e + 3]);
        uint32_t u0 = __ldg(reinterpret_cast<const uint32_t*>(Y + (size_t)p0.x * 64) + lane);
        uint32_t u1 = __ldg(reinterpret_cast<const uint32_t*>(Y + (size_t)p1.x * 64) + lane);
        uint32_t u2 = __ldg(reinterpret_cast<const uint32_t*>(Y + (size_t)p2.x * 64) + lane);
        uint32_t u3 = __ldg(reinterpret_cast<const uint32_t*>(Y + (size_t)p3.x * 64) + lane);
        float v0 = __int_as_float(p0.y), v1 = __int_as_float(p1.y);
        float v2 = __int_as_float(p2.y), v3 = __int_as_float(p3.y);
        float2 f0 = __half22float2(*reinterpret_cast<__half2*>(&u0));
        float2 f1 = __half22float2(*reinterpret_cast<__half2*>(&u1));
        float2 f2 = __half22float2(*reinterpret_cast<__half2*>(&u2));
        float2 f3 = __half22float2(*reinterpret_cast<__half2*>(&u3));
        acc.x = fmaf(v0, f0.x, acc.x); acc.y = fmaf(v0, f0.y, acc.y);
        acc.x = fmaf(v1, f1.x, acc.x); acc.y = fmaf(v1, f1.y, acc.y);
        acc.x = fmaf(v2, f2.x, acc.x); acc.y = fmaf(v2, f2.y, acc.y);
        acc.x = fmaf(v3, f3.x, acc.x); acc.y = fmaf(v3, f3.y, acc.y);
    }
    for (; e < end; ++e) {
        int2 p = __ldg(&g_edges[e]);
        float v = __int_as_float(p.y);
        uint32_t u = __ldg(reinterpret_cast<const uint32_t*>(Y + (size_t)p.x * 64) + lane);
        float2 f = __half22float2(*reinterpret_cast<__half2*>(&u));
        acc.x = fmaf(v, f.x, acc.x); acc.y = fmaf(v, f.y, acc.y);
    }

    float m = fmaxf(acc.x, acc.y);
#pragma unroll
    for (int o = 16; o; o >>= 1) m = fmaxf(m, __shfl_xor_sync(0xffffffffu, m, o));
    float e0 = __expf(acc.x - m);
    float e1 = __expf(acc.y - m);
    float ssum = e0 + e1;
#pragma unroll
    for (int o = 16; o; o >>= 1) ssum += __shfl_xor_sync(0xffffffffu, ssum, o);
    float inv = 1.f / ssum;
    *reinterpret_cast<float2*>(out + (size_t)d * 64 + lane * 2) =
        make_float2(e0 * inv, e1 * inv);
}

// ---------------------------------------------------------------------------
// Launch. Inputs: x, vals, W1, W2, src, dst. Output fp32 [N, 64].
// gemm128 on a forked stream overlapping the CSR build (slot 5 = ncu capture);
// fused gather+gemm64 replaces the old gather128 -> gemm64 pair.
// ---------------------------------------------------------------------------
extern "C" void kernel_launch(void* const* d_in, const int* in_sizes, int n_in,
                              void* d_out, int out_size)
{
    const float* x    = (const float*)d_in[0];
    const float* vals = (const float*)d_in[1];
    const float* W1   = (const float*)d_in[2];
    const float* W2   = (const float*)d_in[3];
    const int*   src  = (const int*)d_in[4];
    const int*   dst  = (const int*)d_in[5];
    float*       out  = (float*)d_out;

    const int M = in_sizes[0] / NF;   // 50000
    const int E = in_sizes[1];        // 800000

    __half *y1h, *y2h;
    int* degp;
    cudaGetSymbolAddress((void**)&y1h, g_y1h);
    cudaGetSymbolAddress((void**)&y2h, g_y2h);
    cudaGetSymbolAddress((void**)&degp, g_deg);

    const int nb = (M + SCAN_B - 1) / SCAN_B;           // 98
    const int gemmBlocks = (M + 127) / 128;

    cudaStream_t s2;
    cudaEvent_t evFork, evJoin;
    cudaStreamCreateWithFlags(&s2, cudaStreamNonBlocking);
    cudaEventCreateWithFlags(&evFork, cudaEventDisableTiming);
    cudaEventCreateWithFlags(&evJoin, cudaEventDisableTiming);

    cudaEventRecord(evFork, 0);
    cudaStreamWaitEvent(s2, evFork, 0);

    // --- chain A (CSR build) on the default stream ---
    cudaMemsetAsync(degp, 0, M * sizeof(int));                              // 1
    hist_kernel<<<(E + 255) / 256, 256>>>(dst, E);                          // 2
    scan1_kernel<<<nb, SCAN_B>>>(M);                                        // 3
    scan23_kernel<<<(M + 255) / 256, 256>>>(M, nb, E);                      // 4
    // --- chain B (gemm128) on s2; submitted 5th for the ncu slot ---
    gemm_tc_kernel<128, false><<<gemmBlocks, 256, 0, s2>>>(x, W1, y1h, M);  // 5 (ncu slot)
    cudaEventRecord(evJoin, s2);
    permute_kernel<<<(E + 255) / 256, 256>>>(src, dst, vals, E);            // 6

    // --- join: fused gather+gemm64 needs both chains ---
    cudaStreamWaitEvent(0, evJoin, 0);
    gather_gemm64_kernel<<<FUSE_BLOCKS, 256>>>(y1h, W2, y2h, M);            // 7
    gather64_softmax_kernel<<<(M * 32 + 255) / 256, 256>>>(y2h, out, M);    // 8
}

// round 17
// speedup vs baseline: 1.4314x; 1.4314x over previous
#include <cuda_runtime.h>
#include <cuda_fp16.h>
#include <cstdint>
#include <cstddef>

#define MAXN 50000
#define MAXE 800000
#define NF   128
#define NOUT 64
#define SCAN_B 512

// Scratch (no allocations allowed -> __device__ globals).
__device__ uint2 g_y1h[(size_t)MAXN * NF / 4];    // x @ W1^T            (half)
__device__ uint2 g_s1h[(size_t)MAXN * NF / 4];    // gather-spmm(y1)     (half)
__device__ uint2 g_y2h[(size_t)MAXN * NOUT / 4];  // relu(s1) @ W2^T     (half)
__device__ int   g_deg[MAXN];                     // degree counts, then write-cursor
__device__ int   g_off[MAXN + 1];                 // CSR row offsets (by dst)
__device__ int   g_bsum[SCAN_B];                  // scan block sums
__device__ int2  g_edges[MAXE];                   // {src, __float_as_int(val)} by dst

// ---------------------------------------------------------------------------
// CSR build: histogram -> scan1 (per-block) -> scan23 (apply) -> permute
// ---------------------------------------------------------------------------
__global__ void hist_kernel(const int* __restrict__ dst, int E) {
    int i = blockIdx.x * blockDim.x + threadIdx.x;
    if (i < E) atomicAdd(&g_deg[__ldg(dst + i)], 1);
}

__global__ __launch_bounds__(SCAN_B) void scan1_kernel(int n) {
    __shared__ int sh[SCAN_B];
    int t = threadIdx.x;
    int i = blockIdx.x * SCAN_B + t;
    int v = (i < n) ? g_deg[i] : 0;
    sh[t] = v;
    __syncthreads();
#pragma unroll
    for (int o = 1; o < SCAN_B; o <<= 1) {
        int u = (t >= o) ? sh[t - o] : 0;
        __syncthreads();
        sh[t] += u;
        __syncthreads();
    }
    if (i <= n && i < MAXN + 1) g_off[i] = sh[t] - v;
    if (t == SCAN_B - 1) g_bsum[blockIdx.x] = sh[t];
}

__global__ void scan23_kernel(int n, int nb, int E) {
    __shared__ int pref[256];
    int t = threadIdx.x;
    if (t == 0) {
        int run = 0;
        for (int b = 0; b < nb; ++b) { pref[b] = run; run += g_bsum[b]; }
    }
    __syncthreads();
    int i = blockIdx.x * blockDim.x + t;
    if (i < n) {
        int o = g_off[i] + pref[i >> 9];
        g_off[i] = o;
        g_deg[i] = o;
    }
    if (i == 0) g_off[n] = E;
}

__global__ void permute_kernel(const int* __restrict__ src, const int* __restrict__ dst,
                               const float* __restrict__ vals, int E) {
    int e = blockIdx.x * blockDim.x + threadIdx.x;
    if (e >= E) return;
    int pos = atomicAdd(&g_deg[__ldg(dst + e)], 1);
    g_edges[pos] = make_int2(__ldg(src + e), __float_as_int(__ldg(vals + e)));
}

// ---------------------------------------------------------------------------
// bf16 / mma / ldmatrix helpers
// ---------------------------------------------------------------------------
__device__ __forceinline__ uint32_t bf16x2_rn(float f0, float f1) {
    uint32_t r;
    asm("cvt.rn.bf16x2.f32 %0, %1, %2;" : "=r"(r) : "f"(f1), "f"(f0));
    return r;
}

template <bool RELU>
__device__ __forceinline__ void cvt8_bf(const float* v, uint32_t* hw, uint32_t* lw) {
#pragma unroll
    for (int p = 0; p < 4; ++p) {
        float f0 = v[2 * p], f1 = v[2 * p + 1];
        if (RELU) { f0 = fmaxf(f0, 0.f); f1 = fmaxf(f1, 0.f); }
        uint32_t h = bf16x2_rn(f0, f1);
        float h0 = __uint_as_float(h << 16);
        float h1 = __uint_as_float(h & 0xFFFF0000u);
        uint32_t l = bf16x2_rn(f0 - h0, f1 - h1);
        hw[p] = h; lw[p] = l;
    }
}

__device__ __forceinline__ void mma_bf16(float* d, const uint32_t* a, uint32_t b0, uint32_t b1) {
    asm volatile(
        "mma.sync.aligned.m16n8k16.row.col.f32.bf16.bf16.f32 "
        "{%0,%1,%2,%3}, {%4,%5,%6,%7}, {%8,%9}, {%0,%1,%2,%3};"
        : "+f"(d[0]), "+f"(d[1]), "+f"(d[2]), "+f"(d[3])
        : "r"(a[0]), "r"(a[1]), "r"(a[2]), "r"(a[3]), "r"(b0), "r"(b1));
}

__device__ __forceinline__ void ldm_x4(uint32_t* r, uint32_t saddr) {
    asm volatile("ldmatrix.sync.aligned.m8n8.x4.shared.b16 {%0,%1,%2,%3}, [%4];"
                 : "=r"(r[0]), "=r"(r[1]), "=r"(r[2]), "=r"(r[3]) : "r"(saddr));
}

// 16 consecutive elements -> float v[16], for fp32 or fp16 A operands.
__device__ __forceinline__ void load16f(const float* p, float* v) {
    *reinterpret_cast<float4*>(v)      = *reinterpret_cast<const float4*>(p);
    *reinterpret_cast<float4*>(v + 4)  = *reinterpret_cast<const float4*>(p + 4);
    *reinterpret_cast<float4*>(v + 8)  = *reinterpret_cast<const float4*>(p + 8);
    *reinterpret_cast<float4*>(v + 12) = *reinterpret_cast<const float4*>(p + 12);
}
__device__ __forceinline__ void load16f(const __half* p, float* v) {
    uint4 r0 = *reinterpret_cast<const uint4*>(p);
    uint4 r1 = *reinterpret_cast<const uint4*>(p + 8);
    const uint32_t w[8] = {r0.x, r0.y, r0.z, r0.w, r1.x, r1.y, r1.z, r1.w};
#pragma unroll
    for (int j = 0; j < 8; ++j) {
        float2 f = __half22float2(*reinterpret_cast<const __half2*>(&w[j]));
        v[2 * j] = f.x; v[2 * j + 1] = f.y;
    }
}

// ---------------------------------------------------------------------------
// C[M, NCOLS] (fp16) = act(A)[M, 128] @ W[NCOLS, 128]^T via 3xBF16 MMA
// (hi/lo split). A may be fp32 or fp16 (fp16 splits exactly into bf16 hi+lo).
// ---------------------------------------------------------------------------
template <int NCOLS, bool RELU_IN, typename AT>
__global__ __launch_bounds__(256) void gemm_tc_kernel(
    const AT* __restrict__ A, const float* __restrict__ W,
    __half* __restrict__ C, int M)
{
    constexpr int BK   = 32;
    constexpr int STRD = 20;
    constexpr int NT   = NCOLS / 16;

    __shared__ __align__(16) uint32_t As_hi[128 * STRD];
    __shared__ __align__(16) uint32_t As_lo[128 * STRD];
    __shared__ __align__(16) uint32_t Bs_hi[NCOLS * STRD];
    __shared__ __align__(16) uint32_t Bs_lo[NCOLS * STRD];

    const int tid  = threadIdx.x;
    const int wid  = tid >> 5;
    const int lane = tid & 31;
    const int g    = lane >> 2;
    const int t    = lane & 3;
    const int warp_m = wid >> 1;
    const int warp_n = wid & 1;
    const int blockRow = blockIdx.x * 128;

    float acc[2][NT][4];
#pragma unroll
    for (int mt = 0; mt < 2; ++mt)
#pragma unroll
        for (int nt = 0; nt < NT; ++nt)
#pragma unroll
            for (int i = 0; i < 4; ++i) acc[mt][nt][i] = 0.f;

    const uint32_t sAhi = (uint32_t)__cvta_generic_to_shared(As_hi);
    const uint32_t sAlo = (uint32_t)__cvta_generic_to_shared(As_lo);
    const uint32_t sBhi = (uint32_t)__cvta_generic_to_shared(Bs_hi);
    const uint32_t sBlo = (uint32_t)__cvta_generic_to_shared(Bs_lo);

    const int  arow  = tid >> 1;
    const int  akoff = (tid & 1) * 16;
    const int  gArow = blockRow + arow;
    const bool aok   = (gArow < M);

    const int a_lr = lane & 15;
    const int a_kb = (lane >> 4) * 16;
    const int b_lr = (lane & 7) + ((lane >> 4) << 3);
    const int b_kb = ((lane >> 3) & 1) * 16;

    for (int k0 = 0; k0 < 128; k0 += BK) {
        {
            float v[16];
#pragma unroll
            for (int j = 0; j < 16; ++j) v[j] = 0.f;
            if (aok) load16f(A + (size_t)gArow * 128 + k0 + akoff, v);
            uint32_t hw[8], lw[8];
            cvt8_bf<RELU_IN>(v, hw, lw);
            cvt8_bf<RELU_IN>(v + 8, hw + 4, lw + 4);
            int wo = arow * STRD + (akoff >> 1);
            *reinterpret_cast<uint4*>(&As_hi[wo])     = make_uint4(hw[0], hw[1], hw[2], hw[3]);
            *reinterpret_cast<uint4*>(&As_hi[wo + 4]) = make_uint4(hw[4], hw[5], hw[6], hw[7]);
            *reinterpret_cast<uint4*>(&As_lo[wo])     = make_uint4(lw[0], lw[1], lw[2], lw[3]);
            *reinterpret_cast<uint4*>(&As_lo[wo + 4]) = make_uint4(lw[4], lw[5], lw[6], lw[7]);
        }
        if (NCOLS == 128) {
            int brow  = tid >> 1;
            int bkoff = (tid & 1) * 16;
            float v[16];
            load16f(W + (size_t)brow * 128 + k0 + bkoff, v);
            uint32_t hw[8], lw[8];
            cvt8_bf<false>(v, hw, lw);
            cvt8_bf<false>(v + 8, hw + 4, lw + 4);
            int wo = brow * STRD + (bkoff >> 1);
            *reinterpret_cast<uint4*>(&Bs_hi[wo])     = make_uint4(hw[0], hw[1], hw[2], hw[3]);
            *reinterpret_cast<uint4*>(&Bs_hi[wo + 4]) = make_uint4(hw[4], hw[5], hw[6], hw[7]);
            *reinterpret_cast<uint4*>(&Bs_lo[wo])     = make_uint4(lw[0], lw[1], lw[2], lw[3]);
            *reinterpret_cast<uint4*>(&Bs_lo[wo + 4]) = make_uint4(lw[4], lw[5], lw[6], lw[7]);
        } else {
            int brow  = tid >> 2;
            int bkoff = (tid & 3) * 8;
            float v[8];
            const float* wp = W + (size_t)brow * 128 + k0 + bkoff;
            *reinterpret_cast<float4*>(v)     = *reinterpret_cast<const float4*>(wp);
            *reinterpret_cast<float4*>(v + 4) = *reinterpret_cast<const float4*>(wp + 4);
            uint32_t hw[4], lw[4];
            cvt8_bf<false>(v, hw, lw);
            int wo = brow * STRD + (bkoff >> 1);
            *reinterpret_cast<uint4*>(&Bs_hi[wo]) = make_uint4(hw[0], hw[1], hw[2], hw[3]);
            *reinterpret_cast<uint4*>(&Bs_lo[wo]) = make_uint4(lw[0], lw[1], lw[2], lw[3]);
        }
        __syncthreads();

#pragma unroll
        for (int ks = 0; ks < 2; ++ks) {
            const int kbyte = ks * 32;
            uint32_t ah[2][4], al[2][4];
#pragma unroll
            for (int mt = 0; mt < 2; ++mt) {
                uint32_t off = (uint32_t)((warp_m * 32 + mt * 16 + a_lr) * STRD) * 4u + kbyte + a_kb;
                ldm_x4(ah[mt], sAhi + off);
                ldm_x4(al[mt], sAlo + off);
            }
#pragma unroll
            for (int ntp = 0; ntp < NT / 2; ++ntp) {
                int nbase = warp_n * (NCOLS / 2) + ntp * 16;
                uint32_t off = (uint32_t)((nbase + b_lr) * STRD) * 4u + kbyte + b_kb;
                uint32_t bh[4], bl[4];
                ldm_x4(bh, sBhi + off);
                ldm_x4(bl, sBlo + off);
#pragma unroll
                for (int mt = 0; mt < 2; ++mt) {
                    mma_bf16(acc[mt][2 * ntp],     ah[mt], bh[0], bh[1]);
                    mma_bf16(acc[mt][2 * ntp],     ah[mt], bl[0], bl[1]);
                    mma_bf16(acc[mt][2 * ntp],     al[mt], bh[0], bh[1]);
                    mma_bf16(acc[mt][2 * ntp + 1], ah[mt], bh[2], bh[3]);
                    mma_bf16(acc[mt][2 * ntp + 1], ah[mt], bl[2], bl[3]);
                    mma_bf16(acc[mt][2 * ntp + 1], al[mt], bh[2], bh[3]);
                }
            }
        }
        __syncthreads();
    }

#pragma unroll
    for (int mt = 0; mt < 2; ++mt) {
#pragma unroll
        for (int half = 0; half < 2; ++half) {
            int row = blockRow + warp_m * 32 + mt * 16 + half * 8 + g;
            if (row < M) {
#pragma unroll
                for (int nt = 0; nt < NT; ++nt) {
                    int col = warp_n * (NCOLS / 2) + nt * 8 + 2 * t;
                    __half2 h = __float22half2_rn(
                        make_float2(acc[mt][nt][half * 2], acc[mt][nt][half * 2 + 1]));
                    *reinterpret_cast<__half2*>(C + (size_t)row * NCOLS + col) = h;
                }
            }
        }
    }
}

// ---------------------------------------------------------------------------
// Gather SPMM, 128-wide fp16 input -> fp16 output: warp/node, fp32 accumulate.
// ---------------------------------------------------------------------------
__global__ __launch_bounds__(256) void gather128_kernel(
    const __half* __restrict__ Y, __half* __restrict__ S, int n)
{
    int gid  = blockIdx.x * blockDim.x + threadIdx.x;
    int d    = gid >> 5;
    int lane = threadIdx.x & 31;
    if (d >= n) return;
    int beg = g_off[d], end = g_off[d + 1];

    float4 acc = make_float4(0.f, 0.f, 0.f, 0.f);
    int e = beg;
    for (; e + 3 < end; e += 4) {
        int2 p0 = __ldg(&g_edges[e]);
        int2 p1 = __ldg(&g_edges[e + 1]);
        int2 p2 = __ldg(&g_edges[e + 2]);
        int2 p3 = __ldg(&g_edges[e + 3]);
        uint2 u0 = __ldg(reinterpret_cast<const uint2*>(Y + (size_t)p0.x * 128) + lane);
        uint2 u1 = __ldg(reinterpret_cast<const uint2*>(Y + (size_t)p1.x * 128) + lane);
        uint2 u2 = __ldg(reinterpret_cast<const uint2*>(Y + (size_t)p2.x * 128) + lane);
        uint2 u3 = __ldg(reinterpret_cast<const uint2*>(Y + (size_t)p3.x * 128) + lane);
        float v0 = __int_as_float(p0.y), v1 = __int_as_float(p1.y);
        float v2 = __int_as_float(p2.y), v3 = __int_as_float(p3.y);
        float2 a0 = __half22float2(*reinterpret_cast<__half2*>(&u0.x));
        float2 b0 = __half22float2(*reinterpret_cast<__half2*>(&u0.y));
        float2 a1 = __half22float2(*reinterpret_cast<__half2*>(&u1.x));
        float2 b1 = __half22float2(*reinterpret_cast<__half2*>(&u1.y));
        float2 a2 = __half22float2(*reinterpret_cast<__half2*>(&u2.x));
        float2 b2 = __half22float2(*reinterpret_cast<__half2*>(&u2.y));
        float2 a3 = __half22float2(*reinterpret_cast<__half2*>(&u3.x));
        float2 b3 = __half22float2(*reinterpret_cast<__half2*>(&u3.y));
        acc.x = fmaf(v0, a0.x, acc.x); acc.y = fmaf(v0, a0.y, acc.y);
        acc.z = fmaf(v0, b0.x, acc.z); acc.w = fmaf(v0, b0.y, acc.w);
        acc.x = fmaf(v1, a1.x, acc.x); acc.y = fmaf(v1, a1.y, acc.y);
        acc.z = fmaf(v1, b1.x, acc.z); acc.w = fmaf(v1, b1.y, acc.w);
        acc.x = fmaf(v2, a2.x, acc.x); acc.y = fmaf(v2, a2.y, acc.y);
        acc.z = fmaf(v2, b2.x, acc.z); acc.w = fmaf(v2, b2.y, acc.w);
        acc.x = fmaf(v3, a3.x, acc.x); acc.y = fmaf(v3, a3.y, acc.y);
        acc.z = fmaf(v3, b3.x, acc.z); acc.w = fmaf(v3, b3.y, acc.w);
    }
    for (; e < end; ++e) {
        int2 p = __ldg(&g_edges[e]);
        float v = __int_as_float(p.y);
        uint2 u = __ldg(reinterpret_cast<const uint2*>(Y + (size_t)p.x * 128) + lane);
        float2 a = __half22float2(*reinterpret_cast<__half2*>(&u.x));
        float2 b = __half22float2(*reinterpret_cast<__half2*>(&u.y));
        acc.x = fmaf(v, a.x, acc.x); acc.y = fmaf(v, a.y, acc.y);
        acc.z = fmaf(v, b.x, acc.z); acc.w = fmaf(v, b.y, acc.w);
    }
    // lane holds cols [4*lane, 4*lane+3]; store as 2x half2 (8 bytes)
    __half2 h0 = __float22half2_rn(make_float2(acc.x, acc.y));
    __half2 h1 = __float22half2_rn(make_float2(acc.z, acc.w));
    uint2 packed = make_uint2(*reinterpret_cast<uint32_t*>(&h0),
                              *reinterpret_cast<uint32_t*>(&h1));
    *reinterpret_cast<uint2*>(S + (size_t)d * 128 + lane * 4) = packed;
}

// ---------------------------------------------------------------------------
// Gather SPMM, 64-wide fp16 input, fused row softmax: warp/node, 2 halfs/lane.
// ---------------------------------------------------------------------------
__global__ __launch_bounds__(256) void gather64_softmax_kernel(
    const __half* __restrict__ Y, float* __restrict__ out, int n)
{
    int gid  = blockIdx.x * blockDim.x + threadIdx.x;
    int d    = gid >> 5;
    int lane = threadIdx.x & 31;
    if (d >= n) return;
    int beg = g_off[d], end = g_off[d + 1];

    float2 acc = make_float2(0.f, 0.f);
    int e = beg;
    for (; e + 3 < end; e += 4) {
        int2 p0 = __ldg(&g_edges[e]);
        int2 p1 = __ldg(&g_edges[e + 1]);
        int2 p2 = __ldg(&g_edges[e + 2]);
        int2 p3 = __ldg(&g_edges[e + 3]);
        uint32_t u0 = __ldg(reinterpret_cast<const uint32_t*>(Y + (size_t)p0.x * 64) + lane);
        uint32_t u1 = __ldg(reinterpret_cast<const uint32_t*>(Y + (size_t)p1.x * 64) + lane);
        uint32_t u2 = __ldg(reinterpret_cast<const uint32_t*>(Y + (size_t)p2.x * 64) + lane);
        uint32_t u3 = __ldg(reinterpret_cast<const uint32_t*>(Y + (size_t)p3.x * 64) + lane);
        float v0 = __int_as_float(p0.y), v1 = __int_as_float(p1.y);
        float v2 = __int_as_float(p2.y), v3 = __int_as_float(p3.y);
        float2 f0 = __half22float2(*reinterpret_cast<__half2*>(&u0));
        float2 f1 = __half22float2(*reinterpret_cast<__half2*>(&u1));
        float2 f2 = __half22float2(*reinterpret_cast<__half2*>(&u2));
        float2 f3 = __half22float2(*reinterpret_cast<__half2*>(&u3));
        acc.x = fmaf(v0, f0.x, acc.x); acc.y = fmaf(v0, f0.y, acc.y);
        acc.x = fmaf(v1, f1.x, acc.x); acc.y = fmaf(v1, f1.y, acc.y);
        acc.x = fmaf(v2, f2.x, acc.x); acc.y = fmaf(v2, f2.y, acc.y);
        acc.x = fmaf(v3, f3.x, acc.x); acc.y = fmaf(v3, f3.y, acc.y);
    }
    for (; e < end; ++e) {
        int2 p = __ldg(&g_edges[e]);
        float v = __int_as_float(p.y);
        uint32_t u = __ldg(reinterpret_cast<const uint32_t*>(Y + (size_t)p.x * 64) + lane);
        float2 f = __half22float2(*reinterpret_cast<__half2*>(&u));
        acc.x = fmaf(v, f.x, acc.x); acc.y = fmaf(v, f.y, acc.y);
    }

    float m = fmaxf(acc.x, acc.y);
#pragma unroll
    for (int o = 16; o; o >>= 1) m = fmaxf(m, __shfl_xor_sync(0xffffffffu, m, o));
    float e0 = __expf(acc.x - m);
    float e1 = __expf(acc.y - m);
    float ssum = e0 + e1;
#pragma unroll
    for (int o = 16; o; o >>= 1) ssum += __shfl_xor_sync(0xffffffffu, ssum, o);
    float inv = 1.f / ssum;
    *reinterpret_cast<float2*>(out + (size_t)d * 64 + lane * 2) =
        make_float2(e0 * inv, e1 * inv);
}

// ---------------------------------------------------------------------------
// Launch. Inputs: x, vals, W1, W2, src, dst. Output fp32 [N, 64].
// R14 structure: CSR || gemm128 (stream fork), then gather128 -> gemm64 ->
// gather64+softmax. s1 held in fp16 (exact bf16 hi/lo split downstream).
// ---------------------------------------------------------------------------
extern "C" void kernel_launch(void* const* d_in, const int* in_sizes, int n_in,
                              void* d_out, int out_size)
{
    const float* x    = (const float*)d_in[0];
    const float* vals = (const float*)d_in[1];
    const float* W1   = (const float*)d_in[2];
    const float* W2   = (const float*)d_in[3];
    const int*   src  = (const int*)d_in[4];
    const int*   dst  = (const int*)d_in[5];
    float*       out  = (float*)d_out;

    const int M = in_sizes[0] / NF;   // 50000
    const int E = in_sizes[1];        // 800000

    __half *y1h, *s1h, *y2h;
    int* degp;
    cudaGetSymbolAddress((void**)&y1h, g_y1h);
    cudaGetSymbolAddress((void**)&s1h, g_s1h);
    cudaGetSymbolAddress((void**)&y2h, g_y2h);
    cudaGetSymbolAddress((void**)&degp, g_deg);

    const int nb = (M + SCAN_B - 1) / SCAN_B;           // 98
    const int gemmBlocks = (M + 127) / 128;

    cudaStream_t s2;
    cudaEvent_t evFork, evJoin;
    cudaStreamCreateWithFlags(&s2, cudaStreamNonBlocking);
    cudaEventCreateWithFlags(&evFork, cudaEventDisableTiming);
    cudaEventCreateWithFlags(&evJoin, cudaEventDisableTiming);

    cudaEventRecord(evFork, 0);
    cudaStreamWaitEvent(s2, evFork, 0);

    // --- chain A (CSR build) on the default stream ---
    cudaMemsetAsync(degp, 0, M * sizeof(int));                                    // 1
    hist_kernel<<<(E + 255) / 256, 256>>>(dst, E);                                // 2
    scan1_kernel<<<nb, SCAN_B>>>(M);                                              // 3
    scan23_kernel<<<(M + 255) / 256, 256>>>(M, nb, E);                            // 4
    // --- chain B (gemm128) on s2; submitted 5th for the ncu slot ---
    gemm_tc_kernel<128, false, float><<<gemmBlocks, 256, 0, s2>>>(x, W1, y1h, M); // 5 (ncu slot)
    cudaEventRecord(evJoin, s2);
    permute_kernel<<<(E + 255) / 256, 256>>>(src, dst, vals, E);                  // 6

    // --- join: serial tail ---
    cudaStreamWaitEvent(0, evJoin, 0);
    gather128_kernel<<<(M * 32 + 255) / 256, 256>>>(y1h, s1h, M);                 // 7
    gemm_tc_kernel<64, true, __half><<<gemmBlocks, 256>>>(s1h, W2, y2h, M);       // 8
    gather64_softmax_kernel<<<(M * 32 + 255) / 256, 256>>>(y2h, out, M);          // 9
}